// round 10
// baseline (speedup 1.0000x reference)
#include <cuda_runtime.h>
#include <cuda_fp16.h>
#include <math_constants.h>
#include <cstdint>

// Problem constants (match reference)
#define D         128
#define N_SRC_MAX 50000
#define N_DST_MAX 50000
#define E_MAX     1600000
#define INV_SCALE 0.25f          // 1/sqrt(128/8) = 1/4

// ---------------- scratch (no allocations allowed) ----------------
__device__ __align__(128) float  g_K2[N_SRC_MAX * D];   // src_feat @ M^T
__device__ __align__(128) __half g_Vh[N_SRC_MAX * D];
__device__ __align__(128) float  g_c[N_SRC_MAX];        // per-src bias term s.(Wk^T bq)
__device__ __align__(128) float  g_M[D * D];            // Wq^T @ Wk
__device__ __align__(128) float  g_u[D];                // Wk^T bq
__device__ __align__(128) float  g_zero[D];             // stays 0 (static init)
__device__ __align__(128) int    g_count[N_DST_MAX];
__device__ __align__(128) int    g_start[N_DST_MAX + 1];
__device__ __align__(128) int    g_cursor[N_DST_MAX];
__device__ __align__(128) int    g_perm_src[E_MAX];
__device__ __align__(128) int    g_bsum[128];
__device__ int g_is64;

// ---------------- helpers ----------------
__device__ __forceinline__ int load_idx(const void* p, int i) {
    if (g_is64) return (int)((const long long*)p)[i];
    return ((const int*)p)[i];
}
__device__ __forceinline__ void fma2(unsigned long long& d,
                                     unsigned long long a, unsigned long long b) {
    asm("fma.rn.f32x2 %0, %1, %2, %0;" : "+l"(d) : "l"(a), "l"(b));
}
__device__ __forceinline__ unsigned long long pack2(float x) {
    unsigned long long r;
    asm("mov.b64 %0, {%1, %1};" : "=l"(r) : "f"(x));
    return r;
}

// ---------------- tiny precompute: M = Wq^T @ Wk ----------------
// block i computes row M[i][*]; 128 threads.
__global__ __launch_bounds__(128) void mmat_kernel(
    const float* __restrict__ Wq, const float* __restrict__ Wk)
{
    __shared__ float wq[128];
    int i = blockIdx.x;
    wq[threadIdx.x] = Wq[threadIdx.x * 128 + i];   // Wq[o][i]
    __syncthreads();
    int j = threadIdx.x;
    float acc = 0.0f;
    #pragma unroll 8
    for (int o = 0; o < 128; o++)
        acc += wq[o] * __ldg(&Wk[o * 128 + j]);
    g_M[i * 128 + j] = acc;
}

// u = Wk^T bq  (1 block, 128 threads)
__global__ __launch_bounds__(128) void uvec_kernel(
    const float* __restrict__ Wk, const float* __restrict__ bq)
{
    int j = threadIdx.x;
    float acc = 0.0f;
    #pragma unroll 8
    for (int o = 0; o < 128; o++)
        acc += __ldg(&bq[o]) * __ldg(&Wk[o * 128 + j]);
    g_u[j] = acc;
}

// ---------------- dtype detection ----------------
__global__ void detect_idx_kernel(const void* src_idx, const void* dst_idx,
                                  int n_src, int n_dst, int E) {
    if (threadIdx.x == 0) g_is64 = 1;
    __syncthreads();
    int i = threadIdx.x;
    int limit = (E / 2 < 64) ? E / 2 : 64;
    if (i < limit) {
        long long s = ((const long long*)src_idx)[i];
        long long d = ((const long long*)dst_idx)[i];
        bool ok = (s >= 0 && s < n_src && d >= 0 && d < n_dst);
        if (!ok) atomicExch(&g_is64, 0);
    }
}

__global__ void zero_counts_kernel(int n_dst) {
    int i = blockIdx.x * blockDim.x + threadIdx.x;
    if (i < n_dst) g_count[i] = 0;
}

__global__ __launch_bounds__(256) void hist_kernel(const void* __restrict__ dst_idx, int E) {
    int i = blockIdx.x * blockDim.x + threadIdx.x;
    if (i < E) atomicAdd(&g_count[load_idx(dst_idx, i)], 1);
}

// ---------------- parallel exclusive scan (3 kernels) ----------------
__global__ __launch_bounds__(256) void scan_bsum_kernel(int n_dst) {
    int t = threadIdx.x;
    int base = blockIdx.x * 1024 + t * 4;
    int v = 0;
    #pragma unroll
    for (int j = 0; j < 4; j++) {
        int i = base + j;
        if (i < n_dst) v += g_count[i];
    }
    #pragma unroll
    for (int off = 16; off; off >>= 1) v += __shfl_xor_sync(0xFFFFFFFFu, v, off);
    __shared__ int ws[8];
    if ((t & 31) == 0) ws[t >> 5] = v;
    __syncthreads();
    if (t < 8) {
        int u = ws[t];
        #pragma unroll
        for (int off = 4; off; off >>= 1) u += __shfl_xor_sync(0xFFu, u, off);
        if (t == 0) g_bsum[blockIdx.x] = u;
    }
}

__global__ __launch_bounds__(128) void scan_top_kernel(int nblocks) {
    __shared__ int s[128];
    int t = threadIdx.x;
    s[t] = (t < nblocks) ? g_bsum[t] : 0;
    __syncthreads();
    for (int off = 1; off < 128; off <<= 1) {
        int v = (t >= off) ? s[t - off] : 0;
        __syncthreads();
        s[t] += v;
        __syncthreads();
    }
    int excl = (t == 0) ? 0 : s[t - 1];
    if (t < nblocks) g_bsum[t] = excl;
}

__global__ __launch_bounds__(256) void scan_apply_kernel(int n_dst, int E) {
    __shared__ int ws[8];
    int t = threadIdx.x;
    int lane = t & 31, wid = t >> 5;
    int base = blockIdx.x * 1024 + t * 4;
    int c[4];
    int s_local = 0;
    #pragma unroll
    for (int j = 0; j < 4; j++) {
        int i = base + j;
        c[j] = (i < n_dst) ? g_count[i] : 0;
        s_local += c[j];
    }
    int v = s_local;
    #pragma unroll
    for (int off = 1; off < 32; off <<= 1) {
        int u = __shfl_up_sync(0xFFFFFFFFu, v, off);
        if (lane >= off) v += u;
    }
    if (lane == 31) ws[wid] = v;
    __syncthreads();
    if (t < 8) {
        int u = ws[t];
        #pragma unroll
        for (int off = 1; off < 8; off <<= 1) {
            int x = __shfl_up_sync(0xFFu, u, off);
            if (t >= off) u += x;
        }
        ws[t] = u;
    }
    __syncthreads();
    int run = v - s_local + (wid ? ws[wid - 1] : 0) + g_bsum[blockIdx.x];
    #pragma unroll
    for (int j = 0; j < 4; j++) {
        int i = base + j;
        if (i < n_dst) {
            g_start[i]  = run;
            g_cursor[i] = run;
            run += c[j];
        }
    }
    if (blockIdx.x == 0 && t == 0) g_start[n_dst] = E;
}

__global__ __launch_bounds__(256) void permute_kernel(
    const void* __restrict__ src_idx, const void* __restrict__ dst_idx, int E)
{
    int i = blockIdx.x * blockDim.x + threadIdx.x;
    if (i < E) {
        int s = load_idx(src_idx, i);
        int d = load_idx(dst_idx, i);
        int pos = atomicAdd(&g_cursor[d], 1);
        g_perm_src[pos] = s;
    }
}

// ---------------- merged projection (FFMA2): K2 (fp32 + c_s) and V (fp16) ----------------
#define XT_STRIDE 66
#define WT_STRIDE 132
#define PROJ_SMEM ((128 * XT_STRIDE + 128 * WT_STRIDE) * 4)

__global__ __launch_bounds__(256) void proj2_kernel(
    const float* __restrict__ src_feat,
    const float* __restrict__ Wv, const float* __restrict__ bv_,
    int n_src, int blocks_k2)
{
    extern __shared__ float sm[];
    float* Xt = sm;                        // [128 k][66]
    float* Wt = sm + 128 * XT_STRIDE;      // [128 k][132]

    const int tid = threadIdx.x;
    const int bid = blockIdx.x;

    const float *W, *B;
    int row0;
    bool k2_mode;
    if (bid < blocks_k2) {
        W = g_M; B = g_zero; row0 = bid * 64; k2_mode = true;
    } else {
        W = Wv;  B = bv_;    row0 = (bid - blocks_k2) * 64; k2_mode = false;
    }
    const int N = n_src;

    #pragma unroll 4
    for (int idx = tid; idx < 128 * 128; idx += 256) {
        int o = idx >> 7, k = idx & 127;
        Wt[k * WT_STRIDE + o] = W[idx];
    }
    #pragma unroll
    for (int idx = tid; idx < 64 * 32; idx += 256) {
        int r = idx >> 5, c4 = idx & 31;
        int row = row0 + r;
        float4 v = (row < N) ? ((const float4*)src_feat)[(size_t)row * 32 + c4]
                             : make_float4(0.f, 0.f, 0.f, 0.f);
        Xt[(c4 * 4 + 0) * XT_STRIDE + r] = v.x;
        Xt[(c4 * 4 + 1) * XT_STRIDE + r] = v.y;
        Xt[(c4 * 4 + 2) * XT_STRIDE + r] = v.z;
        Xt[(c4 * 4 + 3) * XT_STRIDE + r] = v.w;
    }
    __syncthreads();

    const int tcol = tid & 31;
    const int trow = tid >> 5;

    unsigned long long acc[4][4];
    #pragma unroll
    for (int p = 0; p < 4; p++)
        #pragma unroll
        for (int j = 0; j < 4; j++) acc[p][j] = 0ULL;

    #pragma unroll 4
    for (int k = 0; k < 128; k++) {
        float4 w = *(const float4*)&Wt[k * WT_STRIDE + tcol * 4];
        unsigned long long wp0 = pack2(w.x), wp1 = pack2(w.y),
                           wp2 = pack2(w.z), wp3 = pack2(w.w);
        const unsigned long long* xrow =
            (const unsigned long long*)&Xt[k * XT_STRIDE + trow * 8];
        #pragma unroll
        for (int p = 0; p < 4; p++) {
            unsigned long long xp = xrow[p];
            fma2(acc[p][0], xp, wp0);
            fma2(acc[p][1], xp, wp1);
            fma2(acc[p][2], xp, wp2);
            fma2(acc[p][3], xp, wp3);
        }
    }

    float4 bias = *(const float4*)&B[tcol * 4];
    #pragma unroll
    for (int p = 0; p < 4; p++) {
        float2 a0 = *(float2*)&acc[p][0];
        float2 a1 = *(float2*)&acc[p][1];
        float2 a2 = *(float2*)&acc[p][2];
        float2 a3 = *(float2*)&acc[p][3];
        int row_e = row0 + trow * 8 + 2 * p;
        float4 oe = make_float4(a0.x + bias.x, a1.x + bias.y, a2.x + bias.z, a3.x + bias.w);
        float4 oo = make_float4(a0.y + bias.x, a1.y + bias.y, a2.y + bias.z, a3.y + bias.w);
        if (k2_mode) {
            if (row_e < N)     ((float4*)g_K2)[(size_t)row_e * 32 + tcol] = oe;
            if (row_e + 1 < N) ((float4*)g_K2)[(size_t)(row_e + 1) * 32 + tcol] = oo;
        } else {
            if (row_e < N) {
                __half2 h0 = __floats2half2_rn(oe.x, oe.y);
                __half2 h1 = __floats2half2_rn(oe.z, oe.w);
                uint2 u; u.x = *(uint32_t*)&h0; u.y = *(uint32_t*)&h1;
                ((uint2*)(g_Vh + (size_t)row_e * 128))[tcol] = u;
            }
            if (row_e + 1 < N) {
                __half2 h0 = __floats2half2_rn(oo.x, oo.y);
                __half2 h1 = __floats2half2_rn(oo.z, oo.w);
                uint2 u; u.x = *(uint32_t*)&h0; u.y = *(uint32_t*)&h1;
                ((uint2*)(g_Vh + (size_t)(row_e + 1) * 128))[tcol] = u;
            }
        }
    }

    // c_s = src[s] . u  (per-src scalar; only K2 blocks)
    if (k2_mode) {
        int r  = tid >> 2;          // row 0..63
        int qq = tid & 3;           // quarter of k-range
        float partial = 0.0f;
        #pragma unroll 8
        for (int kk = 0; kk < 32; kk++) {
            int k = qq * 32 + kk;
            partial += Xt[k * XT_STRIDE + r] * __ldg(&g_u[k]);
        }
        partial += __shfl_xor_sync(0xFFFFFFFFu, partial, 1);
        partial += __shfl_xor_sync(0xFFFFFFFFu, partial, 2);
        int row = row0 + r;
        if (qq == 0 && row < N) g_c[row] = partial;
    }
}

// ---------------- fused attention: one warp per dst, online softmax ----------------
// q comes straight from dst_feat (Q-projection folded into K2 via M).
__global__ __launch_bounds__(256) void attn_kernel(
    const float* __restrict__ dst_feat, float* __restrict__ out, int n_dst)
{
    int w = (blockIdx.x * blockDim.x + threadIdx.x) >> 5;
    if (w >= n_dst) return;
    int lane = threadIdx.x & 31;

    int start = g_start[w];
    int end   = g_start[w + 1];

    float4 q = __ldg(((const float4*)dst_feat) + (size_t)w * 32 + lane);

    float m = -CUDART_INF_F;
    float denom = 0.0f;
    float4 acc = make_float4(0.f, 0.f, 0.f, 0.f);

    for (int p = start; p < end; ++p) {
        int s = __ldg(&g_perm_src[p]);

        float4 k = ((const float4*)(g_K2 + (size_t)s * D))[lane];
        uint2 vv = ((const uint2*)(g_Vh + (size_t)s * D))[lane];
        float2 v01 = __half22float2(*(__half2*)&vv.x);
        float2 v23 = __half22float2(*(__half2*)&vv.y);

        float dot = q.x * k.x + q.y * k.y + q.z * k.z + q.w * k.w;
        #pragma unroll
        for (int off = 16; off > 0; off >>= 1)
            dot += __shfl_xor_sync(0xFFFFFFFFu, dot, off);

        float sc = (dot + __ldg(&g_c[s])) * INV_SCALE;
        float newm = fmaxf(m, sc);
        float scale = __expf(m - newm);
        float wgt   = __expf(sc - newm);
        denom = denom * scale + wgt;
        acc.x = acc.x * scale + wgt * v01.x;
        acc.y = acc.y * scale + wgt * v01.y;
        acc.z = acc.z * scale + wgt * v23.x;
        acc.w = acc.w * scale + wgt * v23.y;
        m = newm;
    }

    float inv = (denom > 0.0f) ? (1.0f / denom) : 0.0f;
    float4 r = make_float4(acc.x * inv, acc.y * inv, acc.z * inv, acc.w * inv);
    ((float4*)(out + (size_t)w * D))[lane] = r;
}

// ---------------- launch ----------------
extern "C" void kernel_launch(void* const* d_in, const int* in_sizes, int n_in,
                              void* d_out, int out_size)
{
    const float* src_feat = (const float*)d_in[0];
    const float* dst_feat = (const float*)d_in[1];
    const void*  src_idx  = d_in[2];
    const void*  dst_idx  = d_in[3];
    const float* Wq = (const float*)d_in[4];
    const float* bq = (const float*)d_in[5];
    const float* Wk = (const float*)d_in[6];
    const float* bk = (const float*)d_in[7];   // folded per-dst -> cancels in softmax
    const float* Wv = (const float*)d_in[8];
    const float* bv = (const float*)d_in[9];
    float* out = (float*)d_out;

    int n_src = in_sizes[0] / D;
    int n_dst = in_sizes[1] / D;
    int E     = in_sizes[2];
    (void)bk;

    static cudaStream_t s2 = nullptr;
    static cudaEvent_t evFork = nullptr, evM = nullptr, evJoin = nullptr;
    static int attr_set = 0;
    if (!attr_set) {
        cudaFuncSetAttribute(proj2_kernel, cudaFuncAttributeMaxDynamicSharedMemorySize, PROJ_SMEM);
        cudaStreamCreateWithFlags(&s2, cudaStreamNonBlocking);
        cudaEventCreateWithFlags(&evFork, cudaEventDisableTiming);
        cudaEventCreateWithFlags(&evM, cudaEventDisableTiming);
        cudaEventCreateWithFlags(&evJoin, cudaEventDisableTiming);
        attr_set = 1;
    }

    // Fork: stream B does the tiny M/u precompute, then the index/sort chain.
    cudaEventRecord(evFork, 0);
    cudaStreamWaitEvent(s2, evFork, 0);

    mmat_kernel<<<128, 128, 0, s2>>>(Wq, Wk);
    uvec_kernel<<<1, 128, 0, s2>>>(Wk, bq);
    cudaEventRecord(evM, s2);

    detect_idx_kernel<<<1, 64, 0, s2>>>(src_idx, dst_idx, n_src, n_dst, E);
    zero_counts_kernel<<<(n_dst + 255) / 256, 256, 0, s2>>>(n_dst);
    hist_kernel<<<(E + 255) / 256, 256, 0, s2>>>(dst_idx, E);
    int scan_blocks = (n_dst + 1023) / 1024;
    scan_bsum_kernel<<<scan_blocks, 256, 0, s2>>>(n_dst);
    scan_top_kernel<<<1, 128, 0, s2>>>(scan_blocks);
    scan_apply_kernel<<<scan_blocks, 256, 0, s2>>>(n_dst, E);
    permute_kernel<<<(E + 255) / 256, 256, 0, s2>>>(src_idx, dst_idx, E);
    cudaEventRecord(evJoin, s2);

    // Stream A: merged K2 + V projection (waits only on M/u precompute).
    int blocks_k2 = (n_src + 63) / 64;
    int blocks_v  = (n_src + 63) / 64;
    cudaStreamWaitEvent(0, evM, 0);
    proj2_kernel<<<blocks_k2 + blocks_v, 256, PROJ_SMEM>>>(
        src_feat, Wv, bv, n_src, blocks_k2);

    // Join: attention needs K2/V/c and the sorted edge lists.
    cudaStreamWaitEvent(0, evJoin, 0);
    attn_kernel<<<(n_dst + 7) / 8, 256>>>(dst_feat, out, n_dst);
}

// round 11
// speedup vs baseline: 1.0794x; 1.0794x over previous
#include <cuda_runtime.h>
#include <cuda_fp16.h>
#include <math_constants.h>
#include <cstdint>

// Problem constants (match reference)
#define D         128
#define N_SRC_MAX 50000
#define N_DST_MAX 50000
#define E_MAX     1600000
#define INV_SCALE 0.25f          // 1/sqrt(128/8) = 1/4

// ---------------- scratch (no allocations allowed) ----------------
__device__ __align__(128) float  g_Q[N_DST_MAX * D];
__device__ __align__(128) float  g_K[N_SRC_MAX * D];
__device__ __align__(128) __half g_Vh[N_SRC_MAX * D];
__device__ __align__(128) int    g_count[N_DST_MAX];
__device__ __align__(128) int    g_start[N_DST_MAX + 1];
__device__ __align__(128) int    g_cursor[N_DST_MAX];
__device__ __align__(128) int    g_perm_src[E_MAX];
__device__ __align__(128) int    g_bsum[128];
__device__ int g_is64;

// ---------------- helpers ----------------
__device__ __forceinline__ int load_idx(const void* p, int i) {
    if (g_is64) return (int)((const long long*)p)[i];
    return ((const int*)p)[i];
}
__device__ __forceinline__ void fma2(unsigned long long& d,
                                     unsigned long long a, unsigned long long b) {
    asm("fma.rn.f32x2 %0, %1, %2, %0;" : "+l"(d) : "l"(a), "l"(b));
}
__device__ __forceinline__ unsigned long long pack2(float x) {
    unsigned long long r;
    asm("mov.b64 %0, {%1, %1};" : "=l"(r) : "f"(x));
    return r;
}

// ---------------- dtype detection ----------------
__global__ void detect_idx_kernel(const void* src_idx, const void* dst_idx,
                                  int n_src, int n_dst, int E) {
    if (threadIdx.x == 0) g_is64 = 1;
    __syncthreads();
    int i = threadIdx.x;
    int limit = (E / 2 < 64) ? E / 2 : 64;
    if (i < limit) {
        long long s = ((const long long*)src_idx)[i];
        long long d = ((const long long*)dst_idx)[i];
        bool ok = (s >= 0 && s < n_src && d >= 0 && d < n_dst);
        if (!ok) atomicExch(&g_is64, 0);
    }
}

__global__ void zero_counts_kernel(int n_dst) {
    int i = blockIdx.x * blockDim.x + threadIdx.x;
    if (i < n_dst) g_count[i] = 0;
}

__global__ __launch_bounds__(256) void hist_kernel(const void* __restrict__ dst_idx, int E) {
    int i = blockIdx.x * blockDim.x + threadIdx.x;
    if (i < E) atomicAdd(&g_count[load_idx(dst_idx, i)], 1);
}

// ---------------- parallel exclusive scan (3 kernels) ----------------
__global__ __launch_bounds__(256) void scan_bsum_kernel(int n_dst) {
    int t = threadIdx.x;
    int base = blockIdx.x * 1024 + t * 4;
    int v = 0;
    #pragma unroll
    for (int j = 0; j < 4; j++) {
        int i = base + j;
        if (i < n_dst) v += g_count[i];
    }
    #pragma unroll
    for (int off = 16; off; off >>= 1) v += __shfl_xor_sync(0xFFFFFFFFu, v, off);
    __shared__ int ws[8];
    if ((t & 31) == 0) ws[t >> 5] = v;
    __syncthreads();
    if (t < 8) {
        int u = ws[t];
        #pragma unroll
        for (int off = 4; off; off >>= 1) u += __shfl_xor_sync(0xFFu, u, off);
        if (t == 0) g_bsum[blockIdx.x] = u;
    }
}

__global__ __launch_bounds__(128) void scan_top_kernel(int nblocks) {
    __shared__ int s[128];
    int t = threadIdx.x;
    s[t] = (t < nblocks) ? g_bsum[t] : 0;
    __syncthreads();
    for (int off = 1; off < 128; off <<= 1) {
        int v = (t >= off) ? s[t - off] : 0;
        __syncthreads();
        s[t] += v;
        __syncthreads();
    }
    int excl = (t == 0) ? 0 : s[t - 1];
    if (t < nblocks) g_bsum[t] = excl;
}

__global__ __launch_bounds__(256) void scan_apply_kernel(int n_dst, int E) {
    __shared__ int ws[8];
    int t = threadIdx.x;
    int lane = t & 31, wid = t >> 5;
    int base = blockIdx.x * 1024 + t * 4;
    int c[4];
    int s_local = 0;
    #pragma unroll
    for (int j = 0; j < 4; j++) {
        int i = base + j;
        c[j] = (i < n_dst) ? g_count[i] : 0;
        s_local += c[j];
    }
    int v = s_local;
    #pragma unroll
    for (int off = 1; off < 32; off <<= 1) {
        int u = __shfl_up_sync(0xFFFFFFFFu, v, off);
        if (lane >= off) v += u;
    }
    if (lane == 31) ws[wid] = v;
    __syncthreads();
    if (t < 8) {
        int u = ws[t];
        #pragma unroll
        for (int off = 1; off < 8; off <<= 1) {
            int x = __shfl_up_sync(0xFFu, u, off);
            if (t >= off) u += x;
        }
        ws[t] = u;
    }
    __syncthreads();
    int run = v - s_local + (wid ? ws[wid - 1] : 0) + g_bsum[blockIdx.x];
    #pragma unroll
    for (int j = 0; j < 4; j++) {
        int i = base + j;
        if (i < n_dst) {
            g_start[i]  = run;
            g_cursor[i] = run;
            run += c[j];
        }
    }
    if (blockIdx.x == 0 && t == 0) g_start[n_dst] = E;
}

__global__ __launch_bounds__(256) void permute_kernel(
    const void* __restrict__ src_idx, const void* __restrict__ dst_idx, int E)
{
    int i = blockIdx.x * blockDim.x + threadIdx.x;
    if (i < E) {
        int s = load_idx(src_idx, i);
        int d = load_idx(dst_idx, i);
        int pos = atomicAdd(&g_cursor[d], 1);
        g_perm_src[pos] = s;
    }
}

// ---------------- merged projection GEMM (FFMA2), LDS-dedup lane layout ----------------
// Warps tiled 2(rows)x4(cols); lanes tiled 4(row-groups)x8(col-groups).
// Within a warp only 8 lanes carry distinct W addresses and 4 lanes distinct X
// addresses -> smem crossbar broadcast-dedup cuts LDS traffic ~3x vs col-linear map.
#define XT_STRIDE 66
#define WT_STRIDE 132
#define PROJ_SMEM ((128 * XT_STRIDE + 128 * WT_STRIDE) * 4)
__global__ __launch_bounds__(256) void proj3_kernel(
    const float* __restrict__ dst_feat, const float* __restrict__ src_feat,
    const float* __restrict__ Wq, const float* __restrict__ bq_,
    const float* __restrict__ Wk, const float* __restrict__ bk_,
    const float* __restrict__ Wv, const float* __restrict__ bv_,
    int n_dst, int n_src, int blocks_q, int blocks_k)
{
    extern __shared__ float sm[];
    float* Xt = sm;                        // [128 k][66]
    float* Wt = sm + 128 * XT_STRIDE;      // [128 k][132]

    const int tid = threadIdx.x;
    const int bid = blockIdx.x;

    const float *X, *W, *B;
    float* Y = nullptr;
    int N, row0;
    bool v_half = false;
    if (bid < blocks_q) {
        X = dst_feat; W = Wq; B = bq_; Y = g_Q; N = n_dst; row0 = bid * 64;
    } else if (bid < blocks_q + blocks_k) {
        X = src_feat; W = Wk; B = bk_; Y = g_K; N = n_src; row0 = (bid - blocks_q) * 64;
    } else {
        X = src_feat; W = Wv; B = bv_; N = n_src; row0 = (bid - blocks_q - blocks_k) * 64;
        v_half = true;
    }

    #pragma unroll 4
    for (int idx = tid; idx < 128 * 128; idx += 256) {
        int o = idx >> 7, k = idx & 127;
        Wt[k * WT_STRIDE + o] = W[idx];
    }
    #pragma unroll
    for (int idx = tid; idx < 64 * 32; idx += 256) {
        int r = idx >> 5, c4 = idx & 31;
        int row = row0 + r;
        float4 v = (row < N) ? ((const float4*)X)[(size_t)row * 32 + c4]
                             : make_float4(0.f, 0.f, 0.f, 0.f);
        Xt[(c4 * 4 + 0) * XT_STRIDE + r] = v.x;
        Xt[(c4 * 4 + 1) * XT_STRIDE + r] = v.y;
        Xt[(c4 * 4 + 2) * XT_STRIDE + r] = v.z;
        Xt[(c4 * 4 + 3) * XT_STRIDE + r] = v.w;
    }
    __syncthreads();

    const int lane    = tid & 31;
    const int wid     = tid >> 5;
    const int warpRow = wid >> 2;          // 0..1 : 32-row slab
    const int warpCol = wid & 3;           // 0..3 : 32-col slab
    const int colLane = lane & 7;          // 0..7 : 4-col group within slab
    const int rowLane = lane >> 3;         // 0..3 : 8-row group within slab

    const int col0 = warpCol * 32 + colLane * 4;   // 4 output cols
    const int r0   = warpRow * 32 + rowLane * 8;   // 8 output rows (4 pairs)

    unsigned long long acc[4][4];          // [row pair p][col j]
    #pragma unroll
    for (int p = 0; p < 4; p++)
        #pragma unroll
        for (int j = 0; j < 4; j++) acc[p][j] = 0ULL;

    #pragma unroll 4
    for (int k = 0; k < 128; k++) {
        float4 w = *(const float4*)&Wt[k * WT_STRIDE + col0];
        unsigned long long wp0 = pack2(w.x), wp1 = pack2(w.y),
                           wp2 = pack2(w.z), wp3 = pack2(w.w);
        const unsigned long long* xrow =
            (const unsigned long long*)&Xt[k * XT_STRIDE + r0];
        #pragma unroll
        for (int p = 0; p < 4; p++) {
            unsigned long long xp = xrow[p];   // {x_{r0+2p}, x_{r0+2p+1}}
            fma2(acc[p][0], xp, wp0);
            fma2(acc[p][1], xp, wp1);
            fma2(acc[p][2], xp, wp2);
            fma2(acc[p][3], xp, wp3);
        }
    }

    float4 bias = *(const float4*)&B[col0];
    #pragma unroll
    for (int p = 0; p < 4; p++) {
        float2 a0 = *(float2*)&acc[p][0];
        float2 a1 = *(float2*)&acc[p][1];
        float2 a2 = *(float2*)&acc[p][2];
        float2 a3 = *(float2*)&acc[p][3];
        int row_e = row0 + r0 + 2 * p;
        float4 oe = make_float4(a0.x + bias.x, a1.x + bias.y, a2.x + bias.z, a3.x + bias.w);
        float4 oo = make_float4(a0.y + bias.x, a1.y + bias.y, a2.y + bias.z, a3.y + bias.w);
        if (v_half) {
            if (row_e < N) {
                __half2 h0 = __floats2half2_rn(oe.x, oe.y);
                __half2 h1 = __floats2half2_rn(oe.z, oe.w);
                uint2 u; u.x = *(uint32_t*)&h0; u.y = *(uint32_t*)&h1;
                ((uint2*)(g_Vh + (size_t)row_e * 128))[col0 >> 2] = u;
            }
            if (row_e + 1 < N) {
                __half2 h0 = __floats2half2_rn(oo.x, oo.y);
                __half2 h1 = __floats2half2_rn(oo.z, oo.w);
                uint2 u; u.x = *(uint32_t*)&h0; u.y = *(uint32_t*)&h1;
                ((uint2*)(g_Vh + (size_t)(row_e + 1) * 128))[col0 >> 2] = u;
            }
        } else {
            if (row_e < N)     ((float4*)Y)[(size_t)row_e * 32 + (col0 >> 2)] = oe;
            if (row_e + 1 < N) ((float4*)Y)[(size_t)(row_e + 1) * 32 + (col0 >> 2)] = oo;
        }
    }
}

// ---------------- fused attention: one warp per dst, online softmax ----------------
__global__ __launch_bounds__(256) void attn_kernel(float* __restrict__ out, int n_dst)
{
    int w = (blockIdx.x * blockDim.x + threadIdx.x) >> 5;
    if (w >= n_dst) return;
    int lane = threadIdx.x & 31;

    int start = g_start[w];
    int end   = g_start[w + 1];

    float4 q = ((const float4*)(g_Q + (size_t)w * D))[lane];

    float m = -CUDART_INF_F;
    float denom = 0.0f;
    float4 acc = make_float4(0.f, 0.f, 0.f, 0.f);

    for (int p = start; p < end; ++p) {
        int s = __ldg(&g_perm_src[p]);

        float4 k = ((const float4*)(g_K + (size_t)s * D))[lane];
        uint2 vv = ((const uint2*)(g_Vh + (size_t)s * D))[lane];
        float2 v01 = __half22float2(*(__half2*)&vv.x);
        float2 v23 = __half22float2(*(__half2*)&vv.y);

        float dot = q.x * k.x + q.y * k.y + q.z * k.z + q.w * k.w;
        #pragma unroll
        for (int off = 16; off > 0; off >>= 1)
            dot += __shfl_xor_sync(0xFFFFFFFFu, dot, off);

        float sc = dot * INV_SCALE;
        float newm = fmaxf(m, sc);
        float scale = __expf(m - newm);
        float wgt   = __expf(sc - newm);
        denom = denom * scale + wgt;
        acc.x = acc.x * scale + wgt * v01.x;
        acc.y = acc.y * scale + wgt * v01.y;
        acc.z = acc.z * scale + wgt * v23.x;
        acc.w = acc.w * scale + wgt * v23.y;
        m = newm;
    }

    float inv = (denom > 0.0f) ? (1.0f / denom) : 0.0f;
    float4 r = make_float4(acc.x * inv, acc.y * inv, acc.z * inv, acc.w * inv);
    ((float4*)(out + (size_t)w * D))[lane] = r;
}

// ---------------- launch: fork-join two streams (R8 schedule) ----------------
extern "C" void kernel_launch(void* const* d_in, const int* in_sizes, int n_in,
                              void* d_out, int out_size)
{
    const float* src_feat = (const float*)d_in[0];
    const float* dst_feat = (const float*)d_in[1];
    const void*  src_idx  = d_in[2];
    const void*  dst_idx  = d_in[3];
    const float* Wq = (const float*)d_in[4];
    const float* bq = (const float*)d_in[5];
    const float* Wk = (const float*)d_in[6];
    const float* bk = (const float*)d_in[7];
    const float* Wv = (const float*)d_in[8];
    const float* bv = (const float*)d_in[9];
    float* out = (float*)d_out;

    int n_src = in_sizes[0] / D;
    int n_dst = in_sizes[1] / D;
    int E     = in_sizes[2];

    static cudaStream_t s2 = nullptr;
    static cudaEvent_t evFork = nullptr, evJoin = nullptr;
    static int attr_set = 0;
    if (!attr_set) {
        cudaFuncSetAttribute(proj3_kernel, cudaFuncAttributeMaxDynamicSharedMemorySize, PROJ_SMEM);
        cudaStreamCreateWithFlags(&s2, cudaStreamNonBlocking);
        cudaEventCreateWithFlags(&evFork, cudaEventDisableTiming);
        cudaEventCreateWithFlags(&evJoin, cudaEventDisableTiming);
        attr_set = 1;
    }

    // Fork: stream B handles the index/sort chain.
    cudaEventRecord(evFork, 0);
    cudaStreamWaitEvent(s2, evFork, 0);

    detect_idx_kernel<<<1, 64, 0, s2>>>(src_idx, dst_idx, n_src, n_dst, E);
    zero_counts_kernel<<<(n_dst + 255) / 256, 256, 0, s2>>>(n_dst);
    hist_kernel<<<(E + 255) / 256, 256, 0, s2>>>(dst_idx, E);
    int scan_blocks = (n_dst + 1023) / 1024;
    scan_bsum_kernel<<<scan_blocks, 256, 0, s2>>>(n_dst);
    scan_top_kernel<<<1, 128, 0, s2>>>(scan_blocks);
    scan_apply_kernel<<<scan_blocks, 256, 0, s2>>>(n_dst, E);
    permute_kernel<<<(E + 255) / 256, 256, 0, s2>>>(src_idx, dst_idx, E);
    cudaEventRecord(evJoin, s2);

    // Stream A: merged projections (Q, K fp32; V fp16).
    int blocks_q = (n_dst + 63) / 64;
    int blocks_k = (n_src + 63) / 64;
    int blocks_v = (n_src + 63) / 64;
    proj3_kernel<<<blocks_q + blocks_k + blocks_v, 256, PROJ_SMEM>>>(
        dst_feat, src_feat, Wq, bq, Wk, bk, Wv, bv, n_dst, n_src, blocks_q, blocks_k);

    // Join: attention needs Q/K/V and the sorted edge lists.
    cudaStreamWaitEvent(0, evJoin, 0);
    attn_kernel<<<(n_dst + 7) / 8, 256>>>(out, n_dst);
}